// round 4
// baseline (speedup 1.0000x reference)
#include <cuda_runtime.h>
#include <cstdint>

#define SEQ    512
#define BATCH  128
#define INPUT  128
#define HIDDEN 512

#define CLUSTER  8
#define NCHUNK   64      // HIDDEN / CLUSTER
#define BCHUNK   8       // batch rows per cluster
#define THREADS  256
#define WS_STRIDE 65     // padded k-row stride for W slice

// dynamic smem: W slice [512][65] + h double buffer [2][512][8]
#define SMEM_FLOATS (512 * WS_STRIDE + 2 * 512 * 8)
#define SMEM_BYTES  (SMEM_FLOATS * 4)

// ---------------------------------------------------------------------------
// Phase 1: proj[row, n] = sum_k input[row, k] * W_in[n, k]  -> written to d_out
// ---------------------------------------------------------------------------
__global__ __launch_bounds__(256) void proj_kernel(
    const float* __restrict__ A,   // (65536, 128)
    const float* __restrict__ W,   // (512, 128)
    float* __restrict__ C)         // (65536, 512)
{
    __shared__ float As[64][65];
    __shared__ float Bs[64][65];

    const int tid  = threadIdx.x;
    const int tx   = tid & 15;
    const int ty   = tid >> 4;
    const int row0 = blockIdx.x * 64;
    const int n0   = blockIdx.y * 64;

    float acc[4][4] = {};

    for (int k0 = 0; k0 < INPUT; k0 += 64) {
        #pragma unroll
        for (int i = 0; i < 16; i++) {
            int e  = tid + i * 256;
            int r  = e >> 6;
            int kk = e & 63;
            As[kk][r] = A[(row0 + r) * INPUT + k0 + kk];
            Bs[kk][r] = W[(n0 + r) * INPUT + k0 + kk];
        }
        __syncthreads();

        #pragma unroll 8
        for (int k = 0; k < 64; k++) {
            float a[4], b[4];
            #pragma unroll
            for (int i = 0; i < 4; i++) a[i] = As[k][ty * 4 + i];
            #pragma unroll
            for (int j = 0; j < 4; j++) b[j] = Bs[k][tx * 4 + j];
            #pragma unroll
            for (int i = 0; i < 4; i++)
                #pragma unroll
                for (int j = 0; j < 4; j++)
                    acc[i][j] += a[i] * b[j];
        }
        __syncthreads();
    }

    #pragma unroll
    for (int i = 0; i < 4; i++) {
        int row = row0 + ty * 4 + i;
        #pragma unroll
        for (int j = 0; j < 4; j++)
            C[row * HIDDEN + n0 + tx * 4 + j] = acc[i][j];
    }
}

// ---------------------------------------------------------------------------
// Phase 2: persistent cluster kernel. 16 clusters x 8 CTAs. One CTA per SM.
//   cluster c: batch rows [8c, 8c+8); rank r: hidden cols [64r, 64r+64)
//   W slice resident in smem for all 512 steps. relu(h) exchanged via DSMEM
//   multicast stores + one barrier.cluster per step (double-buffered).
// ---------------------------------------------------------------------------
__global__ void __launch_bounds__(THREADS, 1) __cluster_dims__(CLUSTER, 1, 1)
recurrent_kernel(const float* __restrict__ Whid,     // (512, 512)
                 const float* __restrict__ noise,    // (512, 512)
                 float* __restrict__ out)            // (512, 128, 512): proj in, h out
{
    extern __shared__ float sm[];
    float* Ws = sm;                        // [k * 65 + n]
    float* hs = sm + 512 * WS_STRIDE;      // [pp*4096 + k*8 + b]   (relu'd h)

    const int tid = threadIdx.x;
    uint32_t rank;
    asm("mov.u32 %0, %%cluster_ctarank;" : "=r"(rank));
    const int n0    = (int)rank * NCHUNK;
    const int bbase = (blockIdx.x >> 3) * BCHUNK;

    // ---- load W_hid slice (coalesced global read, transposed into smem) ----
    for (int e = tid; e < NCHUNK * 128; e += THREADS) {
        int n  = e >> 7;        // 0..63
        int kq = e & 127;       // float4 index along k
        float4 v = reinterpret_cast<const float4*>(Whid)[(n0 + n) * 128 + kq];
        Ws[(4 * kq + 0) * WS_STRIDE + n] = v.x;
        Ws[(4 * kq + 1) * WS_STRIDE + n] = v.y;
        Ws[(4 * kq + 2) * WS_STRIDE + n] = v.z;
        Ws[(4 * kq + 3) * WS_STRIDE + n] = v.w;
    }
    // ---- zero both h buffers (h0 = 0 -> relu(h0) = 0) ----
    for (int e = tid; e < 2 * 512 * 8; e += THREADS) hs[e] = 0.0f;

    // ---- peer smem addresses for the h buffers ----
    uint32_t hs_addr;
    asm("{ .reg .u64 t; cvta.to.shared.u64 t, %1; cvt.u32.u64 %0, t; }"
        : "=r"(hs_addr) : "l"(hs));
    uint32_t peer[CLUSTER];
    #pragma unroll
    for (int r = 0; r < CLUSTER; r++)
        asm("mapa.shared::cluster.u32 %0, %1, %2;"
            : "=r"(peer[r]) : "r"(hs_addr), "r"(r));

    __syncthreads();
    asm volatile("barrier.cluster.arrive.aligned;" ::: "memory");
    asm volatile("barrier.cluster.wait.aligned;"   ::: "memory");

    // ---- thread -> (batch pair, n) mapping ----
    // warp covers 2 consecutive batch-pairs x 16 n (W reads dedup in-warp)
    const int warp = tid >> 5, lane = tid & 31;
    const int bp   = 2 * (warp & 1) + (lane >> 4);    // 0..3
    const int n    = (warp >> 1) * 16 + (lane & 15);  // 0..63
    const int col  = n0 + n;                          // global hidden index
    const int bglb = bbase + 2 * bp;                  // global batch row (even)

    float rh0 = 0.0f, rh1 = 0.0f;   // raw (pre-relu) hidden state, in registers
    int pp = 0;

    for (int s = 0; s < SEQ; s++) {
        // prefetch proj + noise early (latency hidden by the matvec)
        float* o  = out + ((size_t)s * BATCH + bglb) * HIDDEN + col;
        float x0  = o[0];
        float x1  = o[HIDDEN];
        float nz  = __ldg(&noise[s * HIDDEN + col]);

        const float* hp = hs + pp * 4096 + 2 * bp;
        float acc0 = 0.0f, acc1 = 0.0f;
        #pragma unroll 16
        for (int k = 0; k < HIDDEN; k++) {
            float  w  = Ws[k * WS_STRIDE + n];
            float2 h2 = *reinterpret_cast<const float2*>(hp + k * 8);
            acc0 = fmaf(h2.x, w, acc0);
            acc1 = fmaf(h2.y, w, acc1);
        }

        float hn0 = 0.5f * rh0 + 0.5f * (acc0 + x0 + nz);
        float hn1 = 0.5f * rh1 + 0.5f * (acc1 + x1 + nz);
        rh0 = hn0; rh1 = hn1;
        o[0]      = hn0;          // overwrite proj with hidden state
        o[HIDDEN] = hn1;

        // multicast relu(h_new) chunk into every cluster CTA's next buffer
        float r0 = fmaxf(hn0, 0.0f), r1 = fmaxf(hn1, 0.0f);
        uint32_t off = (uint32_t)(((pp ^ 1) * 4096 + col * 8 + 2 * bp) * 4);
        #pragma unroll
        for (int r = 0; r < CLUSTER; r++)
            asm volatile("st.shared::cluster.v2.f32 [%0], {%1, %2};"
                         :: "r"(peer[r] + off), "f"(r0), "f"(r1) : "memory");

        asm volatile("barrier.cluster.arrive.aligned;" ::: "memory");
        asm volatile("barrier.cluster.wait.aligned;"   ::: "memory");
        pp ^= 1;
    }
}

// ---------------------------------------------------------------------------
// final hidden state tail (tuple output: (output, hidden))
// ---------------------------------------------------------------------------
__global__ void tail_copy_kernel(float* __restrict__ out)
{
    int i = blockIdx.x * blockDim.x + threadIdx.x;
    if (i < BATCH * HIDDEN)
        out[(size_t)SEQ * BATCH * HIDDEN + i] =
            out[(size_t)(SEQ - 1) * BATCH * HIDDEN + i];
}

// ---------------------------------------------------------------------------
extern "C" void kernel_launch(void* const* d_in, const int* in_sizes, int n_in,
                              void* d_out, int out_size)
{
    const float* input = (const float*)d_in[0];   // (512,128,128)
    const float* W_in  = (const float*)d_in[1];   // (512,128)
    const float* W_hid = (const float*)d_in[2];   // (512,512)
    const float* noise = (const float*)d_in[3];   // (512,512)
    float* out = (float*)d_out;

    cudaFuncSetAttribute(recurrent_kernel,
                         cudaFuncAttributeMaxDynamicSharedMemorySize,
                         SMEM_BYTES);

    // Phase 1: input projection into d_out
    {
        dim3 grid((SEQ * BATCH) / 64, HIDDEN / 64);
        proj_kernel<<<grid, 256>>>(input, W_in, out);
    }

    // Phase 2: persistent recurrence (128 CTAs = 16 clusters of 8)
    recurrent_kernel<<<128, THREADS, SMEM_BYTES>>>(W_hid, noise, out);

    // final hidden state tail
    if (out_size >= SEQ * BATCH * HIDDEN + BATCH * HIDDEN) {
        tail_copy_kernel<<<(BATCH * HIDDEN + 255) / 256, 256>>>(out);
    }
}